// round 10
// baseline (speedup 1.0000x reference)
#include <cuda_runtime.h>
#include <cstdint>

// y2[a,d,z] = sum_c ( sum_b x1[a,b,z]*x0[b,c,z] ) * x2[c,d,z]
// All tensors (32,32,32768) fp32 row-major, z contiguous. Lane = one f32x2 z-pair.
// R10: balanced big-tile design. Warp tile 8a x 8c (64 B moved per FFMA2 ->
// L1 floor == fma floor). Block 256 thr covers 16a x 32c x 32 z-pairs;
// y1 tile 128KB smem -> 1 block/SM. Both global streams (av, bv/xv) use the
// R8-proven compile-time double-buffer (zero ALU overhead, distance-1).

#define ZH   16384          // z-pairs (f32x2)
#define SDIM 32

using u64 = unsigned long long;

__device__ __forceinline__ u64 ffma2(u64 a, u64 b, u64 c) {
    u64 d;
    asm("fma.rn.f32x2 %0, %1, %2, %3;" : "=l"(d) : "l"(a), "l"(b), "l"(c));
    return d;
}

__global__ void __launch_bounds__(256, 1)
einnet_fused6_kernel(const u64* __restrict__ x0,
                     const u64* __restrict__ x1,
                     const u64* __restrict__ x2,
                     u64* __restrict__ out)
{
    // y1 tile: [a(16)][c(32)][lane(32)] u64 = 128KB
    extern __shared__ u64 y1s[];

    const int lane = threadIdx.x & 31;
    const int w    = threadIdx.x >> 5;            // 0..7
    const int ag   = (w >> 2) * 8;                // local a base: 0 or 8
    const int cg   = (w & 3) * 8;                 // c/d stripe base: 0,8,16,24
    const int abas = blockIdx.x * 16;             // a-half base (0 or 16)
    const int p    = blockIdx.y * 32 + lane;      // global z-pair

    u64 acc[8][8];
    #pragma unroll
    for (int i = 0; i < 8; i++)
        #pragma unroll
        for (int j = 0; j < 8; j++) acc[i][j] = 0ull;

    // ---------------- Pass 1: y1[a,c] = sum_b x1[a,b] * x0[b,c] ----------------
    const u64* __restrict__ Ap = x1 + (size_t)((abas + ag) * SDIM) * ZH + p;
    const u64* __restrict__ Bp = x0 + (size_t)cg * ZH + p;

    u64 av[2][8], bv[2][8];
    #pragma unroll
    for (int i = 0; i < 8; i++) av[0][i] = Ap[(size_t)(i * SDIM) * ZH];
    #pragma unroll
    for (int j = 0; j < 8; j++) bv[0][j] = Bp[(size_t)j * ZH];

    #pragma unroll
    for (int b = 0; b < SDIM; b++) {
        const int cur = b & 1;           // compile-time after full unroll
        if (b + 1 < SDIM) {              // compile-time guard
            #pragma unroll
            for (int i = 0; i < 8; i++)
                av[cur ^ 1][i] = Ap[(size_t)(i * SDIM + b + 1) * ZH];
            #pragma unroll
            for (int j = 0; j < 8; j++)
                bv[cur ^ 1][j] = Bp[(size_t)((b + 1) * SDIM + j) * ZH];
        }
        #pragma unroll
        for (int i = 0; i < 8; i++)
            #pragma unroll
            for (int j = 0; j < 8; j++)
                acc[i][j] = ffma2(av[cur][i], bv[cur][j], acc[i][j]);
    }

    // store y1 stripe (conflict-free: lane-consecutive 8B)
    #pragma unroll
    for (int i = 0; i < 8; i++)
        #pragma unroll
        for (int j = 0; j < 8; j++)
            y1s[((ag + i) * SDIM + cg + j) * 32 + lane] = acc[i][j];
    __syncthreads();

    // ---------------- Pass 2: y2[a,d] = sum_c y1[a,c] * x2[c,d] ----------------
    #pragma unroll
    for (int i = 0; i < 8; i++)
        #pragma unroll
        for (int j = 0; j < 8; j++) acc[i][j] = 0ull;

    const u64* __restrict__ Cp = x2 + (size_t)cg * ZH + p;

    u64 xv[2][8];
    #pragma unroll
    for (int j = 0; j < 8; j++) xv[0][j] = Cp[(size_t)j * ZH];

    #pragma unroll
    for (int c = 0; c < SDIM; c++) {
        const int cur = c & 1;
        if (c + 1 < SDIM) {
            #pragma unroll
            for (int j = 0; j < 8; j++)
                xv[cur ^ 1][j] = Cp[(size_t)((c + 1) * SDIM + j) * ZH];
        }

        u64 yv[8];
        #pragma unroll
        for (int i = 0; i < 8; i++)
            yv[i] = y1s[((ag + i) * SDIM + c) * 32 + lane];

        #pragma unroll
        for (int i = 0; i < 8; i++)
            #pragma unroll
            for (int j = 0; j < 8; j++)
                acc[i][j] = ffma2(yv[i], xv[cur][j], acc[i][j]);
    }

    u64* __restrict__ Op = out + (size_t)((abas + ag) * SDIM + cg) * ZH + p;
    #pragma unroll
    for (int i = 0; i < 8; i++)
        #pragma unroll
        for (int j = 0; j < 8; j++)
            Op[(size_t)(i * SDIM + j) * ZH] = acc[i][j];
}

extern "C" void kernel_launch(void* const* d_in, const int* in_sizes, int n_in,
                              void* d_out, int out_size)
{
    (void)in_sizes; (void)n_in; (void)out_size;
    const u64* x0 = (const u64*)d_in[0];   // (b, c, Z)
    const u64* x1 = (const u64*)d_in[1];   // (a, b, Z)
    const u64* x2 = (const u64*)d_in[2];   // (c, d, Z)
    u64* out = (u64*)d_out;

    constexpr int SMEM_BYTES = 16 * SDIM * 32 * 8;   // 131072 = 128KB
    cudaFuncSetAttribute(einnet_fused6_kernel,
                         cudaFuncAttributeMaxDynamicSharedMemorySize, SMEM_BYTES);

    // z-tile slow dim: the 2 a-half blocks of one z-tile are co-resident and
    // share x0/x2 slices in L2.
    dim3 grid(2, ZH / 32);
    einnet_fused6_kernel<<<grid, 256, SMEM_BYTES>>>(x0, x1, x2, out);
}

// round 11
// speedup vs baseline: 1.0990x; 1.0990x over previous
#include <cuda_runtime.h>
#include <cstdint>

// y2[a,d,z] = sum_c ( sum_b x1[a,b,z]*x0[b,c,z] ) * x2[c,d,z]
// All tensors (32,32,32768) fp32 row-major, z contiguous. Lane = one f32x2 z-pair.
// R11: 8a x 8c warp tile (byte-efficient, proven in R10) but in SMALL blocks:
// 128 thr / 4 warps, block covers 8a x 32c x 32 z-pairs, y1 = 64KB smem ->
// TWO independent blocks/SM (R10's 254-reg kernel forced 1x256-thr block; two
// 128-thr blocks fit the reg file and decorrelate stalls / overlap phases).
// bv/xv: R8-proven compile-time distance-1 double-buffer. av/yv: load-at-use
// (av is an L1 hit for 3 of 4 warps; no double-buffer -> fewer live regs).

#define ZH   16384          // z-pairs (f32x2)
#define SDIM 32

using u64 = unsigned long long;

__device__ __forceinline__ u64 ffma2(u64 a, u64 b, u64 c) {
    u64 d;
    asm("fma.rn.f32x2 %0, %1, %2, %3;" : "=l"(d) : "l"(a), "l"(b), "l"(c));
    return d;
}

__global__ void __launch_bounds__(128, 2)
einnet_fused7_kernel(const u64* __restrict__ x0,
                     const u64* __restrict__ x1,
                     const u64* __restrict__ x2,
                     u64* __restrict__ out)
{
    // y1 tile: [a(8)][c(32)][lane(32)] u64 = 64KB
    extern __shared__ u64 y1s[];

    const int lane = threadIdx.x & 31;
    const int w    = threadIdx.x >> 5;            // 0..3
    const int cg   = w * 8;                       // c/d stripe base
    const int abas = blockIdx.x * 8;              // a-group base (0,8,16,24)
    const int p    = blockIdx.y * 32 + lane;      // global z-pair

    u64 acc[8][8];
    #pragma unroll
    for (int i = 0; i < 8; i++)
        #pragma unroll
        for (int j = 0; j < 8; j++) acc[i][j] = 0ull;

    // ---------------- Pass 1: y1[a,c] = sum_b x1[a,b] * x0[b,c] ----------------
    const u64* __restrict__ Ap = x1 + (size_t)(abas * SDIM) * ZH + p;
    const u64* __restrict__ Bp = x0 + (size_t)cg * ZH + p;

    u64 bv[2][8];
    #pragma unroll
    for (int j = 0; j < 8; j++) bv[0][j] = Bp[(size_t)j * ZH];

    #pragma unroll
    for (int b = 0; b < SDIM; b++) {
        const int cur = b & 1;           // compile-time after full unroll
        if (b + 1 < SDIM) {              // compile-time guard
            #pragma unroll
            for (int j = 0; j < 8; j++)
                bv[cur ^ 1][j] = Bp[(size_t)((b + 1) * SDIM + j) * ZH];
        }

        u64 av[8];
        #pragma unroll
        for (int i = 0; i < 8; i++) av[i] = Ap[(size_t)(i * SDIM + b) * ZH];

        #pragma unroll
        for (int i = 0; i < 8; i++)
            #pragma unroll
            for (int j = 0; j < 8; j++)
                acc[i][j] = ffma2(av[i], bv[cur][j], acc[i][j]);
    }

    // store y1 stripe (conflict-free: lane-consecutive 8B)
    #pragma unroll
    for (int i = 0; i < 8; i++)
        #pragma unroll
        for (int j = 0; j < 8; j++)
            y1s[(i * SDIM + cg + j) * 32 + lane] = acc[i][j];
    __syncthreads();

    // ---------------- Pass 2: y2[a,d] = sum_c y1[a,c] * x2[c,d] ----------------
    #pragma unroll
    for (int i = 0; i < 8; i++)
        #pragma unroll
        for (int j = 0; j < 8; j++) acc[i][j] = 0ull;

    const u64* __restrict__ Cp = x2 + (size_t)cg * ZH + p;

    u64 xv[2][8];
    #pragma unroll
    for (int j = 0; j < 8; j++) xv[0][j] = Cp[(size_t)j * ZH];

    #pragma unroll
    for (int c = 0; c < SDIM; c++) {
        const int cur = c & 1;
        if (c + 1 < SDIM) {
            #pragma unroll
            for (int j = 0; j < 8; j++)
                xv[cur ^ 1][j] = Cp[(size_t)((c + 1) * SDIM + j) * ZH];
        }

        u64 yv[8];
        #pragma unroll
        for (int i = 0; i < 8; i++)
            yv[i] = y1s[(i * SDIM + c) * 32 + lane];

        #pragma unroll
        for (int i = 0; i < 8; i++)
            #pragma unroll
            for (int j = 0; j < 8; j++)
                acc[i][j] = ffma2(yv[i], xv[cur][j], acc[i][j]);
    }

    u64* __restrict__ Op = out + (size_t)(abas * SDIM + cg) * ZH + p;
    #pragma unroll
    for (int i = 0; i < 8; i++)
        #pragma unroll
        for (int j = 0; j < 8; j++)
            Op[(size_t)(i * SDIM + j) * ZH] = acc[i][j];
}

extern "C" void kernel_launch(void* const* d_in, const int* in_sizes, int n_in,
                              void* d_out, int out_size)
{
    (void)in_sizes; (void)n_in; (void)out_size;
    const u64* x0 = (const u64*)d_in[0];   // (b, c, Z)
    const u64* x1 = (const u64*)d_in[1];   // (a, b, Z)
    const u64* x2 = (const u64*)d_in[2];   // (c, d, Z)
    u64* out = (u64*)d_out;

    constexpr int SMEM_BYTES = 8 * SDIM * 32 * 8;   // 65536 = 64KB
    cudaFuncSetAttribute(einnet_fused7_kernel,
                         cudaFuncAttributeMaxDynamicSharedMemorySize, SMEM_BYTES);

    // z-tile slow dim: the 4 a-group blocks of one z-tile are co-resident
    // (2 per SM) and share x0/x2 slices in L2.
    dim3 grid(4, ZH / 32);
    einnet_fused7_kernel<<<grid, 128, SMEM_BYTES>>>(x0, x1, x2, out);
}